// round 1
// baseline (speedup 1.0000x reference)
#include <cuda_runtime.h>
#include <cstdint>

// IWT (inverse 2x2 Haar): x (B=16, 4C=256, H=128, W=128) fp32 -> out (B, C=64, 2H, 2W)
//
// a = x[:, 0:64], b = x[:, 64:128], c = x[:, 128:192], d = x[:, 192:256]
// h00 = .5(a-b-c+d)  -> out[2h, 2w]
// h01 = .5(a+b-c-d)  -> out[2h, 2w+1]
// h10 = .5(a-b+c-d)  -> out[2h+1, 2w]
// h11 = .5(a+b+c+d)  -> out[2h+1, 2w+1]

#define B_  16
#define C_  64
#define H_  128
#define W_  128
#define PLANE_ (H_ * W_)          // 16384
#define SUBBAND_STRIDE_ (C_ * PLANE_)  // 64 * 16384 = 1048576 (offset between a/b/c/d groups)
#define OW_ (2 * W_)              // 256
#define WQ_ (W_ / 4)              // 32 (float4 groups per input row)

__global__ __launch_bounds__(256)
void iwt_kernel(const float* __restrict__ x, float* __restrict__ out) {
    // Each thread: 4 consecutive w at fixed (b, ch, h).
    // Total threads = B * C * H * WQ = 16*64*128*32 = 4,194,304
    int tid = blockIdx.x * blockDim.x + threadIdx.x;

    int w4   = tid & (WQ_ - 1);          // 0..31
    int rest = tid >> 5;                 // / WQ_
    int h    = rest & (H_ - 1);          // 0..127
    rest >>= 7;                          // / H_
    int ch   = rest & (C_ - 1);          // 0..63
    int b    = rest >> 6;                // 0..15

    // Input base: plane of subband 'a' for (b, ch), row h, col w4*4
    int in_idx = ((b * 256 + ch) * H_ + h) * W_ + (w4 << 2);

    const float4 va = *reinterpret_cast<const float4*>(x + in_idx);
    const float4 vb = *reinterpret_cast<const float4*>(x + in_idx + 1 * SUBBAND_STRIDE_);
    const float4 vc = *reinterpret_cast<const float4*>(x + in_idx + 2 * SUBBAND_STRIDE_);
    const float4 vd = *reinterpret_cast<const float4*>(x + in_idx + 3 * SUBBAND_STRIDE_);

    const float a0 = va.x, a1 = va.y, a2 = va.z, a3 = va.w;
    const float b0 = vb.x, b1 = vb.y, b2 = vb.z, b3 = vb.w;
    const float c0 = vc.x, c1 = vc.y, c2 = vc.z, c3 = vc.w;
    const float d0 = vd.x, d1 = vd.y, d2 = vd.z, d3 = vd.w;

    // Butterfly, 4 lanes
    float h00_0 = 0.5f * (a0 - b0 - c0 + d0);
    float h01_0 = 0.5f * (a0 + b0 - c0 - d0);
    float h10_0 = 0.5f * (a0 - b0 + c0 - d0);
    float h11_0 = 0.5f * (a0 + b0 + c0 + d0);

    float h00_1 = 0.5f * (a1 - b1 - c1 + d1);
    float h01_1 = 0.5f * (a1 + b1 - c1 - d1);
    float h10_1 = 0.5f * (a1 - b1 + c1 - d1);
    float h11_1 = 0.5f * (a1 + b1 + c1 + d1);

    float h00_2 = 0.5f * (a2 - b2 - c2 + d2);
    float h01_2 = 0.5f * (a2 + b2 - c2 - d2);
    float h10_2 = 0.5f * (a2 - b2 + c2 - d2);
    float h11_2 = 0.5f * (a2 + b2 + c2 + d2);

    float h00_3 = 0.5f * (a3 - b3 - c3 + d3);
    float h01_3 = 0.5f * (a3 + b3 - c3 - d3);
    float h10_3 = 0.5f * (a3 - b3 + c3 - d3);
    float h11_3 = 0.5f * (a3 + b3 + c3 + d3);

    // Output: (b, ch, 2h + {0,1}, 2*(w4*4) .. +7) -> 2 rows x 2 float4
    int out_row0 = ((b * C_ + ch) * (2 * H_) + (h << 1)) * OW_ + (w4 << 3);
    int out_row1 = out_row0 + OW_;

    float4 e0 = make_float4(h00_0, h01_0, h00_1, h01_1);
    float4 e1 = make_float4(h00_2, h01_2, h00_3, h01_3);
    float4 o0 = make_float4(h10_0, h11_0, h10_1, h11_1);
    float4 o1 = make_float4(h10_2, h11_2, h10_3, h11_3);

    *reinterpret_cast<float4*>(out + out_row0)     = e0;
    *reinterpret_cast<float4*>(out + out_row0 + 4) = e1;
    *reinterpret_cast<float4*>(out + out_row1)     = o0;
    *reinterpret_cast<float4*>(out + out_row1 + 4) = o1;
}

extern "C" void kernel_launch(void* const* d_in, const int* in_sizes, int n_in,
                              void* d_out, int out_size) {
    const float* x = (const float*)d_in[0];
    float* out = (float*)d_out;

    const int total_threads = B_ * C_ * H_ * WQ_;  // 4,194,304
    const int block = 256;
    const int grid = total_threads / block;        // 16384

    iwt_kernel<<<grid, block>>>(x, out);
}